// round 1
// baseline (speedup 1.0000x reference)
#include <cuda_runtime.h>

// Problem constants
#define DM     1024
#define NHEADS 16
#define HD     64
#define BATCH  2
#define SEQ    1024
#define LCACHE 1024
#define TTOT   2048            // LCACHE + SEQ
#define BH     (BATCH * NHEADS)   // 32
#define MROWS  (BATCH * SEQ)      // 2048

// ---------------------------------------------------------------------------
// Scratch (device globals; no allocation allowed)
// ---------------------------------------------------------------------------
__device__ float g_q  [BH * SEQ * HD];    // Q   [bh][s][64]
__device__ float g_kn [BH * SEQ * HD];    // K_new [bh][s][64]
__device__ float g_vn [BH * SEQ * HD];    // V_new [bh][s][64]
__device__ float g_kt [BH * HD * TTOT];   // K^T  [bh][64][2048]
__device__ float g_att[MROWS * DM];       // attention output [b*s][1024]

// ---------------------------------------------------------------------------
// GEMM: C[M,N] = A[M,1024] * W[N,1024]^T + bias[N]
// 128x128 tile, BK=8, 256 threads, 8x8 microtile.
// headwise=1: scatter output to [bh][s][64] layout (for Q/K/V).
// grid.z selects (W,bias,out) triple so QKV is a single launch.
// ---------------------------------------------------------------------------
__global__ __launch_bounds__(256, 2)
void gemm_xWT(const float* __restrict__ A,
              const float* __restrict__ W0, const float* __restrict__ B0, float* __restrict__ O0,
              const float* __restrict__ W1, const float* __restrict__ B1, float* __restrict__ O1,
              const float* __restrict__ W2, const float* __restrict__ B2, float* __restrict__ O2,
              int headwise)
{
    const float* W = W0; const float* bias = B0; float* out = O0;
    if (blockIdx.z == 1) { W = W1; bias = B1; out = O1; }
    else if (blockIdx.z == 2) { W = W2; bias = B2; out = O2; }

    __shared__ float As[8 * 132];   // [k][m], pad 132 -> conflict-free stores+loads
    __shared__ float Bs[8 * 132];   // [k][n]

    const int tid = threadIdx.x;
    const int m0 = blockIdx.y * 128;
    const int n0 = blockIdx.x * 128;
    const int lr = tid >> 1;          // 0..127
    const int lc = (tid & 1) << 2;    // 0 or 4
    const int tx = tid & 15;
    const int ty = tid >> 4;

    const float* Ag = A + (size_t)(m0 + lr) * DM + lc;
    const float* Wg = W + (size_t)(n0 + lr) * DM + lc;

    float acc[8][8];
#pragma unroll
    for (int i = 0; i < 8; i++)
#pragma unroll
        for (int j = 0; j < 8; j++) acc[i][j] = 0.f;

    for (int k0 = 0; k0 < DM; k0 += 8) {
        float4 av = *(const float4*)(Ag + k0);
        float4 wv = *(const float4*)(Wg + k0);
        As[(lc + 0) * 132 + lr] = av.x;
        As[(lc + 1) * 132 + lr] = av.y;
        As[(lc + 2) * 132 + lr] = av.z;
        As[(lc + 3) * 132 + lr] = av.w;
        Bs[(lc + 0) * 132 + lr] = wv.x;
        Bs[(lc + 1) * 132 + lr] = wv.y;
        Bs[(lc + 2) * 132 + lr] = wv.z;
        Bs[(lc + 3) * 132 + lr] = wv.w;
        __syncthreads();
#pragma unroll
        for (int k = 0; k < 8; k++) {
            float a[8], bb[8];
            *(float4*)&a[0]  = *(const float4*)&As[k * 132 + ty * 8];
            *(float4*)&a[4]  = *(const float4*)&As[k * 132 + ty * 8 + 4];
            *(float4*)&bb[0] = *(const float4*)&Bs[k * 132 + tx * 8];
            *(float4*)&bb[4] = *(const float4*)&Bs[k * 132 + tx * 8 + 4];
#pragma unroll
            for (int i = 0; i < 8; i++)
#pragma unroll
                for (int j = 0; j < 8; j++)
                    acc[i][j] = fmaf(a[i], bb[j], acc[i][j]);
        }
        __syncthreads();
    }

#pragma unroll
    for (int i = 0; i < 8; i++) {
        int m = m0 + ty * 8 + i;
        int bidx = m >> 10, s = m & 1023;
#pragma unroll
        for (int j = 0; j < 8; j += 4) {
            int n = n0 + tx * 8 + j;
            float4 v;
            v.x = acc[i][j + 0] + bias[n + 0];
            v.y = acc[i][j + 1] + bias[n + 1];
            v.z = acc[i][j + 2] + bias[n + 2];
            v.w = acc[i][j + 3] + bias[n + 3];
            if (headwise) {
                int h = n >> 6, d = n & 63;
                *(float4*)&out[(((size_t)bidx * NHEADS + h) * SEQ + s) * HD + d] = v;
            } else {
                *(float4*)&out[(size_t)m * DM + n] = v;
            }
        }
    }
}

// ---------------------------------------------------------------------------
// Build K^T [bh][64][2048] from cache_k (t<1024) / g_kn (t>=1024).
// Classic smem tile transpose, 32x32 tiles, block (32,8).
// ---------------------------------------------------------------------------
__global__ void build_kt(const float* __restrict__ cache_k)
{
    __shared__ float tile[32][33];
    const int bh = blockIdx.z;
    const int t0 = blockIdx.x * 32;
    const int d0 = blockIdx.y * 32;
    const int tx = threadIdx.x;   // 0..31
    const int ty = threadIdx.y;   // 0..7

    const float* src = (t0 < LCACHE)
        ? (cache_k + ((size_t)bh * LCACHE + t0) * HD)
        : (g_kn    + ((size_t)bh * SEQ + (t0 - LCACHE)) * HD);

#pragma unroll
    for (int i = 0; i < 4; i++) {
        int t = ty + i * 8;
        tile[t][tx] = src[(size_t)t * HD + d0 + tx];
    }
    __syncthreads();
#pragma unroll
    for (int i = 0; i < 4; i++) {
        int d = ty + i * 8;
        g_kt[((size_t)bh * HD + d0 + d) * TTOT + t0 + tx] = tile[tx][d];
    }
}

// ---------------------------------------------------------------------------
// Flash attention, fp32. One CTA per (bh, 64-row q tile). 256 threads (16x16),
// 4x4 microtile. Online softmax, causal offset = 1024.
// smem layouts: sQ[d][r] stride 65 (scalar broadcast loads, conflict-free
// transpose stores); sK[d][c] stride 68 (direct rows from g_kt, LDS.128);
// sV[c][d] stride 68 (LDS.128); sP[c][r] stride 65.
// ---------------------------------------------------------------------------
#define ATT_SMEM ((64 * 65 + 64 * 68 + 64 * 68 + 64 * 65) * 4)

__global__ __launch_bounds__(256, 3)
void attn_kernel(const float* __restrict__ cache_v)
{
    extern __shared__ float sm[];
    float* sQ = sm;                    // 64*65
    float* sK = sQ + 64 * 65;          // 64*68
    float* sV = sK + 64 * 68;          // 64*68
    float* sP = sV + 64 * 68;          // 64*65

    const int tid = threadIdx.x;
    const int tx = tid & 15, ty = tid >> 4;
    const int bh = blockIdx.y;
    const int qt = blockIdx.x;
    const int q0 = qt * 64;
    const int r0 = ty * 4;     // q rows owned
    const int c0 = tx * 4;     // kv cols owned (S) / hd cols owned (O)

    // Load Q tile transposed into sQ[d][r]
    const float* qg = g_q + ((size_t)bh * SEQ + q0) * HD;
#pragma unroll
    for (int it = 0; it < 16; it++) {
        int idx = it * 256 + tid;        // 0..4095
        int r = idx >> 6, d = idx & 63;
        sQ[d * 65 + r] = qg[idx];
    }

    float m_[4], l_[4], o_[4][4];
#pragma unroll
    for (int i = 0; i < 4; i++) {
        m_[i] = -1e30f; l_[i] = 0.f;
#pragma unroll
        for (int j = 0; j < 4; j++) o_[i][j] = 0.f;
    }
    __syncthreads();

    const int ntiles = qt + 17;
    const float* ktbase = g_kt + (size_t)bh * HD * TTOT;

    for (int kt = 0; kt < ntiles; kt++) {
        const int t0 = kt * 64;
        const float* vsrc = (t0 < LCACHE)
            ? (cache_v + ((size_t)bh * LCACHE + t0) * HD)
            : (g_vn    + ((size_t)bh * SEQ + (t0 - LCACHE)) * HD);

        // Load K tile (rows of g_kt, already transposed) and V tile
#pragma unroll
        for (int it = 0; it < 4; it++) {
            int idx = it * 256 + tid;        // 0..1023
            int rr = idx >> 4;               // 0..63
            int c4 = (idx & 15) << 2;        // 0..60
            *(float4*)&sK[rr * 68 + c4] = *(const float4*)&ktbase[(size_t)rr * TTOT + t0 + c4];
            *(float4*)&sV[rr * 68 + c4] = *(const float4*)&vsrc[(size_t)rr * HD + c4];
        }
        __syncthreads();

        // S = Q K^T over d=64
        float s[4][4];
#pragma unroll
        for (int i = 0; i < 4; i++)
#pragma unroll
            for (int j = 0; j < 4; j++) s[i][j] = 0.f;

#pragma unroll 4
        for (int k = 0; k < 64; k++) {
            float a0 = sQ[k * 65 + r0 + 0];
            float a1 = sQ[k * 65 + r0 + 1];
            float a2 = sQ[k * 65 + r0 + 2];
            float a3 = sQ[k * 65 + r0 + 3];
            float4 bv = *(const float4*)&sK[k * 68 + c0];
            s[0][0] = fmaf(a0, bv.x, s[0][0]); s[0][1] = fmaf(a0, bv.y, s[0][1]);
            s[0][2] = fmaf(a0, bv.z, s[0][2]); s[0][3] = fmaf(a0, bv.w, s[0][3]);
            s[1][0] = fmaf(a1, bv.x, s[1][0]); s[1][1] = fmaf(a1, bv.y, s[1][1]);
            s[1][2] = fmaf(a1, bv.z, s[1][2]); s[1][3] = fmaf(a1, bv.w, s[1][3]);
            s[2][0] = fmaf(a2, bv.x, s[2][0]); s[2][1] = fmaf(a2, bv.y, s[2][1]);
            s[2][2] = fmaf(a2, bv.z, s[2][2]); s[2][3] = fmaf(a2, bv.w, s[2][3]);
            s[3][0] = fmaf(a3, bv.x, s[3][0]); s[3][1] = fmaf(a3, bv.y, s[3][1]);
            s[3][2] = fmaf(a3, bv.z, s[3][2]); s[3][3] = fmaf(a3, bv.w, s[3][3]);
        }

        // Online softmax (scale 1/sqrt(64)=0.125, causal: t <= q + 1024)
#pragma unroll
        for (int i = 0; i < 4; i++) {
            const int tmax = q0 + r0 + i + LCACHE;   // max allowed t index
            float sv[4];
            float mt = -1e30f;
#pragma unroll
            for (int j = 0; j < 4; j++) {
                float v = s[i][j] * 0.125f;
                if (t0 + c0 + j > tmax) v = -1e30f;
                sv[j] = v;
                mt = fmaxf(mt, v);
            }
#pragma unroll
            for (int off = 8; off; off >>= 1)
                mt = fmaxf(mt, __shfl_xor_sync(0xffffffffu, mt, off));
            float mn = fmaxf(m_[i], mt);
            float f = __expf(m_[i] - mn);
            m_[i] = mn;
            float rs = 0.f;
#pragma unroll
            for (int j = 0; j < 4; j++) {
                float p = __expf(sv[j] - mn);
                sv[j] = p;
                rs += p;
            }
#pragma unroll
            for (int off = 8; off; off >>= 1)
                rs += __shfl_xor_sync(0xffffffffu, rs, off);
            l_[i] = l_[i] * f + rs;
#pragma unroll
            for (int j = 0; j < 4; j++) o_[i][j] *= f;
            // store P transposed: sP[c][r]
#pragma unroll
            for (int j = 0; j < 4; j++) sP[(c0 + j) * 65 + (r0 + i)] = sv[j];
        }
        __syncthreads();

        // O += P V : O[r][d] += sum_c sP[c][r] * sV[c][d]
#pragma unroll 4
        for (int c = 0; c < 64; c++) {
            float a0 = sP[c * 65 + r0 + 0];
            float a1 = sP[c * 65 + r0 + 1];
            float a2 = sP[c * 65 + r0 + 2];
            float a3 = sP[c * 65 + r0 + 3];
            float4 bv = *(const float4*)&sV[c * 68 + c0];
            o_[0][0] = fmaf(a0, bv.x, o_[0][0]); o_[0][1] = fmaf(a0, bv.y, o_[0][1]);
            o_[0][2] = fmaf(a0, bv.z, o_[0][2]); o_[0][3] = fmaf(a0, bv.w, o_[0][3]);
            o_[1][0] = fmaf(a1, bv.x, o_[1][0]); o_[1][1] = fmaf(a1, bv.y, o_[1][1]);
            o_[1][2] = fmaf(a1, bv.z, o_[1][2]); o_[1][3] = fmaf(a1, bv.w, o_[1][3]);
            o_[2][0] = fmaf(a2, bv.x, o_[2][0]); o_[2][1] = fmaf(a2, bv.y, o_[2][1]);
            o_[2][2] = fmaf(a2, bv.z, o_[2][2]); o_[2][3] = fmaf(a2, bv.w, o_[2][3]);
            o_[3][0] = fmaf(a3, bv.x, o_[3][0]); o_[3][1] = fmaf(a3, bv.y, o_[3][1]);
            o_[3][2] = fmaf(a3, bv.z, o_[3][2]); o_[3][3] = fmaf(a3, bv.w, o_[3][3]);
        }
        __syncthreads();
    }

    // Normalize and write to g_att [b*SEQ + q][h*64 + d]
    const int b = bh >> 4, h = bh & 15;
#pragma unroll
    for (int i = 0; i < 4; i++) {
        float inv = 1.0f / l_[i];
        float4 v = make_float4(o_[i][0] * inv, o_[i][1] * inv,
                               o_[i][2] * inv, o_[i][3] * inv);
        *(float4*)&g_att[((size_t)b * SEQ + q0 + r0 + i) * DM + h * HD + c0] = v;
    }
}

// ---------------------------------------------------------------------------
// launch
// ---------------------------------------------------------------------------
extern "C" void kernel_launch(void* const* d_in, const int* in_sizes, int n_in,
                              void* d_out, int out_size)
{
    const float* x  = (const float*)d_in[0];
    const float* ck = (const float*)d_in[1];
    const float* cv = (const float*)d_in[2];
    const float* Wq = (const float*)d_in[3];
    const float* bq = (const float*)d_in[4];
    const float* Wk = (const float*)d_in[5];
    const float* bk = (const float*)d_in[6];
    const float* Wv = (const float*)d_in[7];
    const float* bv = (const float*)d_in[8];
    const float* Wo = (const float*)d_in[9];
    const float* bo = (const float*)d_in[10];
    float* out = (float*)d_out;

    float *gq, *gkn, *gvn, *gatt;
    cudaGetSymbolAddress((void**)&gq,   g_q);
    cudaGetSymbolAddress((void**)&gkn,  g_kn);
    cudaGetSymbolAddress((void**)&gvn,  g_vn);
    cudaGetSymbolAddress((void**)&gatt, g_att);

    // 1) QKV projections (one launch, grid.z selects weight set), headwise out
    dim3 gqkv(DM / 128, MROWS / 128, 3);
    gemm_xWT<<<gqkv, 256>>>(x, Wq, bq, gq, Wk, bk, gkn, Wv, bv, gvn, 1);

    // 2) Build K^T (cache ++ new)
    dim3 gt(TTOT / 32, HD / 32, BH);
    build_kt<<<gt, dim3(32, 8)>>>(ck);

    // 3) Attention
    cudaFuncSetAttribute(attn_kernel, cudaFuncAttributeMaxDynamicSharedMemorySize, ATT_SMEM);
    attn_kernel<<<dim3(SEQ / 64, BH), 256, ATT_SMEM>>>(cv);

    // 4) Output projection (row-major epilogue straight into d_out)
    dim3 gop(DM / 128, MROWS / 128, 1);
    gemm_xWT<<<gop, 256>>>(gatt, Wo, bo, out, Wo, bo, out, Wo, bo, out, 0);
}

// round 4
// speedup vs baseline: 1.4377x; 1.4377x over previous
#include <cuda_runtime.h>
#include <cuda_bf16.h>
#include <cstdint>

#define DM     1024
#define NHEADS 16
#define HD     64
#define BATCH  2
#define SEQ    1024
#define LCACHE 1024
#define TTOT   2048
#define BH     (BATCH * NHEADS)   // 32
#define MROWS  (BATCH * SEQ)      // 2048

// ---------------------------------------------------------------------------
// Scratch (device globals; no allocation allowed)
// ---------------------------------------------------------------------------
__device__ float g_q  [BH * SEQ * HD];
__device__ float g_kn [BH * SEQ * HD];
__device__ float g_vn [BH * SEQ * HD];
__device__ float g_kt [BH * HD * TTOT];
__device__ float g_att[MROWS * DM];
__device__ __nv_bfloat16 g_xhi[MROWS * DM], g_xlo[MROWS * DM];
__device__ __nv_bfloat16 g_whi[4 * DM * DM], g_wlo[4 * DM * DM];
__device__ __nv_bfloat16 g_ahi[MROWS * DM], g_alo[MROWS * DM];

// ---------------------------------------------------------------------------
// PTX helpers — baseline ISA only (compute_103-safe): cp.async, ldmatrix, mma
// ---------------------------------------------------------------------------
__device__ __forceinline__ uint32_t smem_u32(const void* p) {
    uint32_t a;
    asm("{ .reg .u64 t; cvta.to.shared.u64 t, %1; cvt.u32.u64 %0, t; }"
        : "=r"(a) : "l"(p));
    return a;
}
__device__ __forceinline__ void cp16(uint32_t d, const void* s) {
    asm volatile("cp.async.cg.shared.global [%0], [%1], 16;" :: "r"(d), "l"(s) : "memory");
}
__device__ __forceinline__ void cp_commit() {
    asm volatile("cp.async.commit_group;" ::: "memory");
}
template <int N> __device__ __forceinline__ void cp_wait() {
    asm volatile("cp.async.wait_group %0;" :: "n"(N) : "memory");
}
__device__ __forceinline__ void ldmx4(uint32_t* r, uint32_t a) {
    asm volatile("ldmatrix.sync.aligned.m8n8.x4.shared.b16 {%0,%1,%2,%3}, [%4];"
        : "=r"(r[0]), "=r"(r[1]), "=r"(r[2]), "=r"(r[3]) : "r"(a));
}
__device__ __forceinline__ void ldmx2(uint32_t* r, uint32_t a) {
    asm volatile("ldmatrix.sync.aligned.m8n8.x2.shared.b16 {%0,%1}, [%2];"
        : "=r"(r[0]), "=r"(r[1]) : "r"(a));
}
__device__ __forceinline__ void mma16816(float* d, const uint32_t* a, const uint32_t* b) {
    asm volatile(
        "mma.sync.aligned.m16n8k16.row.col.f32.bf16.bf16.f32 "
        "{%0,%1,%2,%3}, {%4,%5,%6,%7}, {%8,%9}, {%0,%1,%2,%3};"
        : "+f"(d[0]), "+f"(d[1]), "+f"(d[2]), "+f"(d[3])
        : "r"(a[0]), "r"(a[1]), "r"(a[2]), "r"(a[3]), "r"(b[0]), "r"(b[1]));
}

// ---------------------------------------------------------------------------
// hi/lo bf16 split kernels
// ---------------------------------------------------------------------------
__global__ void split_kernel(const float* __restrict__ in,
                             __nv_bfloat16* __restrict__ hi,
                             __nv_bfloat16* __restrict__ lo, int n4)
{
    int i = blockIdx.x * blockDim.x + threadIdx.x;
    if (i >= n4) return;
    float4 v = ((const float4*)in)[i];
    __nv_bfloat16 h0 = __float2bfloat16_rn(v.x);
    __nv_bfloat16 h1 = __float2bfloat16_rn(v.y);
    __nv_bfloat16 h2 = __float2bfloat16_rn(v.z);
    __nv_bfloat16 h3 = __float2bfloat16_rn(v.w);
    __nv_bfloat16 l0 = __float2bfloat16_rn(v.x - __bfloat162float(h0));
    __nv_bfloat16 l1 = __float2bfloat16_rn(v.y - __bfloat162float(h1));
    __nv_bfloat16 l2 = __float2bfloat16_rn(v.z - __bfloat162float(h2));
    __nv_bfloat16 l3 = __float2bfloat16_rn(v.w - __bfloat162float(h3));
    ((__nv_bfloat162*)hi)[2 * i]     = __halves2bfloat162(h0, h1);
    ((__nv_bfloat162*)hi)[2 * i + 1] = __halves2bfloat162(h2, h3);
    ((__nv_bfloat162*)lo)[2 * i]     = __halves2bfloat162(l0, l1);
    ((__nv_bfloat162*)lo)[2 * i + 1] = __halves2bfloat162(l2, l3);
}

__global__ void split_w4(const float* __restrict__ w0, const float* __restrict__ w1,
                         const float* __restrict__ w2, const float* __restrict__ w3,
                         __nv_bfloat16* __restrict__ hi, __nv_bfloat16* __restrict__ lo)
{
    int p = blockIdx.y;
    const float* src = (p == 0) ? w0 : (p == 1) ? w1 : (p == 2) ? w2 : w3;
    size_t off2 = (size_t)p * (DM * DM / 2);   // bfloat162 units
    int i = blockIdx.x * blockDim.x + threadIdx.x;   // over DM*DM/4
    float4 v = ((const float4*)src)[i];
    __nv_bfloat16 h0 = __float2bfloat16_rn(v.x);
    __nv_bfloat16 h1 = __float2bfloat16_rn(v.y);
    __nv_bfloat16 h2 = __float2bfloat16_rn(v.z);
    __nv_bfloat16 h3 = __float2bfloat16_rn(v.w);
    __nv_bfloat16 l0 = __float2bfloat16_rn(v.x - __bfloat162float(h0));
    __nv_bfloat16 l1 = __float2bfloat16_rn(v.y - __bfloat162float(h1));
    __nv_bfloat16 l2 = __float2bfloat16_rn(v.z - __bfloat162float(h2));
    __nv_bfloat16 l3 = __float2bfloat16_rn(v.w - __bfloat162float(h3));
    ((__nv_bfloat162*)hi)[off2 + 2 * i]     = __halves2bfloat162(h0, h1);
    ((__nv_bfloat162*)hi)[off2 + 2 * i + 1] = __halves2bfloat162(h2, h3);
    ((__nv_bfloat162*)lo)[off2 + 2 * i]     = __halves2bfloat162(l0, l1);
    ((__nv_bfloat162*)lo)[off2 + 2 * i + 1] = __halves2bfloat162(l2, l3);
}

// ---------------------------------------------------------------------------
// Warp-MMA bf16 GEMM: C[2048,1024] = A * W^T + bias, hi/lo 3-term split.
// CTA 128x128, 8 warps (warp tile 64x32), BK=32, 3-stage cp.async pipeline.
// smem rows padded to 80B for conflict-free ldmatrix.
// ---------------------------------------------------------------------------
#define ST       3
#define CHUNKS   32
#define ROWPAD   80              // bytes per 32-bf16 row (64B data + 16B pad)
#define PLANE_B  (128 * ROWPAD)  // 10240
#define STAGE_B  (4 * PLANE_B)   // Ahi, Alo, Whi, Wlo = 40960
#define GSMEM    (ST * STAGE_B)  // 122880

__global__ __launch_bounds__(256, 1)
void gemm_mma(const __nv_bfloat16* __restrict__ Ahi, const __nv_bfloat16* __restrict__ Alo,
              const __nv_bfloat16* __restrict__ Whi, const __nv_bfloat16* __restrict__ Wlo,
              const float* __restrict__ b0, const float* __restrict__ b1, const float* __restrict__ b2,
              float* __restrict__ o0, float* __restrict__ o1, float* __restrict__ o2,
              int headwise)
{
    extern __shared__ char smem[];
    const uint32_t sb = smem_u32(smem);
    const int tid = threadIdx.x, wid = tid >> 5, lane = tid & 31;
    const int n0 = blockIdx.x * 128, m0 = blockIdx.y * 128, z = blockIdx.z;
    const __nv_bfloat16* Wh = Whi + (size_t)z * DM * DM;
    const __nv_bfloat16* Wl = Wlo + (size_t)z * DM * DM;
    const float* bias = (z == 0) ? b0 : (z == 1) ? b1 : b2;
    float* out = (z == 0) ? o0 : (z == 1) ? o1 : o2;

    const int wm = wid & 1;       // 2 m-blocks of 64
    const int wn = wid >> 1;      // 4 n-blocks of 32

    // ---- chunk loader: 4 planes x 128 rows x 64B, rows padded to 80B
    auto load_chunk = [&](int stage, int koff) {
        const uint32_t base = sb + stage * STAGE_B;
#pragma unroll
        for (int it = 0; it < 8; it++) {
            int g = it * 256 + tid;            // 0..2047 granules of 16B
            int plane = g >> 9;                // 512 granules per plane
            int row = (g >> 2) & 127;
            int c = g & 3;
            uint32_t dst = base + plane * PLANE_B + row * ROWPAD + c * 16;
            const __nv_bfloat16* src;
            if (plane == 0)      src = Ahi + (size_t)(m0 + row) * DM + koff + c * 8;
            else if (plane == 1) src = Alo + (size_t)(m0 + row) * DM + koff + c * 8;
            else if (plane == 2) src = Wh  + (size_t)(n0 + row) * DM + koff + c * 8;
            else                 src = Wl  + (size_t)(n0 + row) * DM + koff + c * 8;
            cp16(dst, src);
        }
        cp_commit();
    };

    // prologue: chunks 0,1 -> stages 0,1
    load_chunk(0, 0);
    load_chunk(1, 32);

    float acc[4][4][4];
#pragma unroll
    for (int i = 0; i < 4; i++)
#pragma unroll
        for (int j = 0; j < 4; j++)
#pragma unroll
            for (int r = 0; r < 4; r++) acc[i][j][r] = 0.f;

    const int lr16 = lane & 15, lc16 = lane >> 4;
    const int br8 = lane & 7, bc8 = (lane >> 3) & 1;

    for (int i = 0; i < CHUNKS; i++) {
        if (i + 2 < CHUNKS) load_chunk((i + 2) % ST, (i + 2) * 32);
        else cp_commit();                 // keep group count uniform
        cp_wait<2>();
        __syncthreads();

        const uint32_t stb = sb + (i % ST) * STAGE_B;
#pragma unroll
        for (int ks = 0; ks < 2; ks++) {
            uint32_t ah[4][4], al[4][4];
#pragma unroll
            for (int mi = 0; mi < 4; mi++) {
                uint32_t ad = stb + (wm * 64 + mi * 16 + lr16) * ROWPAD + ks * 32 + lc16 * 16;
                ldmx4(ah[mi], ad);
                ldmx4(al[mi], ad + PLANE_B);
            }
            uint32_t bh[4][2], bl[4][2];
#pragma unroll
            for (int nj = 0; nj < 4; nj++) {
                uint32_t bd = stb + 2 * PLANE_B + (wn * 32 + nj * 8 + br8) * ROWPAD + ks * 32 + bc8 * 16;
                ldmx2(bh[nj], bd);
                ldmx2(bl[nj], bd + PLANE_B);
            }
#pragma unroll
            for (int mi = 0; mi < 4; mi++)
#pragma unroll
                for (int nj = 0; nj < 4; nj++) {
                    mma16816(acc[mi][nj], ah[mi], bh[nj]);
                    mma16816(acc[mi][nj], ah[mi], bl[nj]);
                    mma16816(acc[mi][nj], al[mi], bh[nj]);
                }
        }
        __syncthreads();
    }

    // ---- epilogue: bias + (optional) headwise scatter; float2 stores
#pragma unroll
    for (int nj = 0; nj < 4; nj++) {
        const int n = n0 + wn * 32 + nj * 8 + (lane & 3) * 2;
        const float bx = bias[n], by = bias[n + 1];
#pragma unroll
        for (int mi = 0; mi < 4; mi++) {
            const int m = m0 + wm * 64 + mi * 16 + (lane >> 2);
            float2 v0 = make_float2(acc[mi][nj][0] + bx, acc[mi][nj][1] + by);
            float2 v1 = make_float2(acc[mi][nj][2] + bx, acc[mi][nj][3] + by);
            if (headwise) {
                const int h = n >> 6, d = n & 63;
                int bi = m >> 10, s = m & 1023;
                *(float2*)&out[(((size_t)bi * NHEADS + h) * SEQ + s) * HD + d] = v0;
                int m2 = m + 8;
                bi = m2 >> 10; s = m2 & 1023;
                *(float2*)&out[(((size_t)bi * NHEADS + h) * SEQ + s) * HD + d] = v1;
            } else {
                *(float2*)&out[(size_t)m * DM + n] = v0;
                *(float2*)&out[(size_t)(m + 8) * DM + n] = v1;
            }
        }
    }
}

// ---------------------------------------------------------------------------
// Build K^T [bh][64][2048] from cache_k (t<1024) / g_kn (t>=1024).
// ---------------------------------------------------------------------------
__global__ void build_kt(const float* __restrict__ cache_k)
{
    __shared__ float tile[32][33];
    const int bh = blockIdx.z;
    const int t0 = blockIdx.x * 32;
    const int d0 = blockIdx.y * 32;
    const int tx = threadIdx.x;
    const int ty = threadIdx.y;

    const float* src = (t0 < LCACHE)
        ? (cache_k + ((size_t)bh * LCACHE + t0) * HD)
        : (g_kn    + ((size_t)bh * SEQ + (t0 - LCACHE)) * HD);

#pragma unroll
    for (int i = 0; i < 4; i++) {
        int t = ty + i * 8;
        tile[t][tx] = src[(size_t)t * HD + d0 + tx];
    }
    __syncthreads();
#pragma unroll
    for (int i = 0; i < 4; i++) {
        int d = ty + i * 8;
        g_kt[((size_t)bh * HD + d0 + d) * TTOT + t0 + tx] = tile[tx][d];
    }
}

// ---------------------------------------------------------------------------
// SIMT flash attention (unchanged from R1)
// ---------------------------------------------------------------------------
#define ATT_SMEM ((64 * 65 + 64 * 68 + 64 * 68 + 64 * 65) * 4)

__global__ __launch_bounds__(256, 3)
void attn_kernel(const float* __restrict__ cache_v)
{
    extern __shared__ float sm[];
    float* sQ = sm;
    float* sK = sQ + 64 * 65;
    float* sV = sK + 64 * 68;
    float* sP = sV + 64 * 68;

    const int tid = threadIdx.x;
    const int tx = tid & 15, ty = tid >> 4;
    const int bh = blockIdx.y;
    const int qt = blockIdx.x;
    const int q0 = qt * 64;
    const int r0 = ty * 4;
    const int c0 = tx * 4;

    const float* qg = g_q + ((size_t)bh * SEQ + q0) * HD;
#pragma unroll
    for (int it = 0; it < 16; it++) {
        int idx = it * 256 + tid;
        int r = idx >> 6, d = idx & 63;
        sQ[d * 65 + r] = qg[idx];
    }

    float m_[4], l_[4], o_[4][4];
#pragma unroll
    for (int i = 0; i < 4; i++) {
        m_[i] = -1e30f; l_[i] = 0.f;
#pragma unroll
        for (int j = 0; j < 4; j++) o_[i][j] = 0.f;
    }
    __syncthreads();

    const int ntiles = qt + 17;
    const float* ktbase = g_kt + (size_t)bh * HD * TTOT;

    for (int kt = 0; kt < ntiles; kt++) {
        const int t0 = kt * 64;
        const float* vsrc = (t0 < LCACHE)
            ? (cache_v + ((size_t)bh * LCACHE + t0) * HD)
            : (g_vn    + ((size_t)bh * SEQ + (t0 - LCACHE)) * HD);

#pragma unroll
        for (int it = 0; it < 4; it++) {
            int idx = it * 256 + tid;
            int rr = idx >> 4;
            int c4 = (idx & 15) << 2;
            *(float4*)&sK[rr * 68 + c4] = *(const float4*)&ktbase[(size_t)rr * TTOT + t0 + c4];
            *(float4*)&sV[rr * 68 + c4] = *(const float4*)&vsrc[(size_t)rr * HD + c4];
        }
        __syncthreads();

        float s[4][4];
#pragma unroll
        for (int i = 0; i < 4; i++)
#pragma unroll
            for (int j = 0; j < 4; j++) s[i][j] = 0.f;

#pragma unroll 4
        for (int k = 0; k < 64; k++) {
            float a0 = sQ[k * 65 + r0 + 0];
            float a1 = sQ[k * 65 + r0 + 1];
            float a2 = sQ[k * 65 + r0 + 2];
            float a3 = sQ[k * 65 + r0 + 3];
            float4 bv = *(const float4*)&sK[k * 68 + c0];
            s[0][0] = fmaf(a0, bv.x, s[0][0]); s[0][1] = fmaf(a0, bv.y, s[0][1]);
            s[0][2] = fmaf(a0, bv.z, s[0][2]); s[0][3] = fmaf(a0, bv.w, s[0][3]);
            s[1][0] = fmaf(a1, bv.x, s[1][0]); s[1][1] = fmaf(a1, bv.y, s[1][1]);
            s[1][2] = fmaf(a1, bv.z, s[1][2]); s[1][3] = fmaf(a1, bv.w, s[1][3]);
            s[2][0] = fmaf(a2, bv.x, s[2][0]); s[2][1] = fmaf(a2, bv.y, s[2][1]);
            s[2][2] = fmaf(a2, bv.z, s[2][2]); s[2][3] = fmaf(a2, bv.w, s[2][3]);
            s[3][0] = fmaf(a3, bv.x, s[3][0]); s[3][1] = fmaf(a3, bv.y, s[3][1]);
            s[3][2] = fmaf(a3, bv.z, s[3][2]); s[3][3] = fmaf(a3, bv.w, s[3][3]);
        }

#pragma unroll
        for (int i = 0; i < 4; i++) {
            const int tmax = q0 + r0 + i + LCACHE;
            float sv[4];
            float mt = -1e30f;
#pragma unroll
            for (int j = 0; j < 4; j++) {
                float v = s[i][j] * 0.125f;
                if (t0 + c0 + j > tmax) v = -1e30f;
                sv[j] = v;
                mt = fmaxf(mt, v);
            }
#pragma unroll
            for (int off = 8; off; off >>= 1)
                mt = fmaxf(mt, __shfl_xor_sync(0xffffffffu, mt, off));
            float mn = fmaxf(m_[i], mt);
            float f = __expf(m_[i] - mn);
            m_[i] = mn;
            float rs = 0.f;
#pragma unroll
            for (int j = 0; j < 4; j++) {
                float p = __expf(sv[j] - mn);
                sv[j] = p;
                rs += p;
            }
#pragma unroll
            for (int off = 8; off; off >>= 1)
                rs += __shfl_xor_sync(0xffffffffu, rs, off);
            l_[i] = l_[i] * f + rs;
#pragma unroll
            for (int j = 0; j < 4; j++) o_[i][j] *= f;
#pragma unroll
            for (int j = 0; j < 4; j++) sP[(c0 + j) * 65 + (r0 + i)] = sv[j];
        }
        __syncthreads();

#pragma unroll 4
        for (int c = 0; c < 64; c++) {
            float a0 = sP[c * 65 + r0 + 0];
            float a1 = sP[c * 65 + r0 + 1];
            float a2 = sP[c * 65 + r0 + 2];
            float a3 = sP[c * 65 + r0 + 3];
            float4 bv = *(const float4*)&sV[c * 68 + c0];
            o_[0][0] = fmaf(a0, bv.x, o_[0][0]); o_[0][1] = fmaf(a0, bv.y, o_[0][1]);
            o_[0][2] = fmaf(a0, bv.z, o_[0][2]); o_[0][3] = fmaf(a0, bv.w, o_[0][3]);
            o_[1][0] = fmaf(a1, bv.x, o_[1][0]); o_[1][1] = fmaf(a1, bv.y, o_[1][1]);
            o_[1][2] = fmaf(a1, bv.z, o_[1][2]); o_[1][3] = fmaf(a1, bv.w, o_[1][3]);
            o_[2][0] = fmaf(a2, bv.x, o_[2][0]); o_[2][1] = fmaf(a2, bv.y, o_[2][1]);
            o_[2][2] = fmaf(a2, bv.z, o_[2][2]); o_[2][3] = fmaf(a2, bv.w, o_[2][3]);
            o_[3][0] = fmaf(a3, bv.x, o_[3][0]); o_[3][1] = fmaf(a3, bv.y, o_[3][1]);
            o_[3][2] = fmaf(a3, bv.z, o_[3][2]); o_[3][3] = fmaf(a3, bv.w, o_[3][3]);
        }
        __syncthreads();
    }

    const int b = bh >> 4, h = bh & 15;
#pragma unroll
    for (int i = 0; i < 4; i++) {
        float inv = 1.0f / l_[i];
        float4 v = make_float4(o_[i][0] * inv, o_[i][1] * inv,
                               o_[i][2] * inv, o_[i][3] * inv);
        *(float4*)&g_att[((size_t)b * SEQ + q0 + r0 + i) * DM + h * HD + c0] = v;
    }
}

// ---------------------------------------------------------------------------
// launch
// ---------------------------------------------------------------------------
extern "C" void kernel_launch(void* const* d_in, const int* in_sizes, int n_in,
                              void* d_out, int out_size)
{
    const float* x  = (const float*)d_in[0];
    const float* ck = (const float*)d_in[1];
    const float* cv = (const float*)d_in[2];
    const float* Wq = (const float*)d_in[3];
    const float* bq = (const float*)d_in[4];
    const float* Wk = (const float*)d_in[5];
    const float* bk = (const float*)d_in[6];
    const float* Wv = (const float*)d_in[7];
    const float* bv = (const float*)d_in[8];
    const float* Wo = (const float*)d_in[9];
    const float* bo = (const float*)d_in[10];
    float* out = (float*)d_out;

    float *gq, *gkn, *gvn, *gatt;
    __nv_bfloat16 *xhi, *xlo, *whi, *wlo, *ahi, *alo;
    cudaGetSymbolAddress((void**)&gq,   g_q);
    cudaGetSymbolAddress((void**)&gkn,  g_kn);
    cudaGetSymbolAddress((void**)&gvn,  g_vn);
    cudaGetSymbolAddress((void**)&gatt, g_att);
    cudaGetSymbolAddress((void**)&xhi,  g_xhi);
    cudaGetSymbolAddress((void**)&xlo,  g_xlo);
    cudaGetSymbolAddress((void**)&whi,  g_whi);
    cudaGetSymbolAddress((void**)&wlo,  g_wlo);
    cudaGetSymbolAddress((void**)&ahi,  g_ahi);
    cudaGetSymbolAddress((void**)&alo,  g_alo);

    cudaFuncSetAttribute(gemm_mma, cudaFuncAttributeMaxDynamicSharedMemorySize, GSMEM);
    cudaFuncSetAttribute(attn_kernel, cudaFuncAttributeMaxDynamicSharedMemorySize, ATT_SMEM);

    // 1) hi/lo splits of activations and weights
    split_kernel<<<(MROWS * DM / 4 + 255) / 256, 256>>>(x, xhi, xlo, MROWS * DM / 4);
    split_w4<<<dim3(DM * DM / 4 / 256, 4), 256>>>(Wq, Wk, Wv, Wo, whi, wlo);

    // 2) QKV projections on tensor cores (headwise epilogue)
    gemm_mma<<<dim3(8, 16, 3), 256, GSMEM>>>(xhi, xlo, whi, wlo,
                                             bq, bk, bv, gq, gkn, gvn, 1);

    // 3) Build K^T
    build_kt<<<dim3(TTOT / 32, HD / 32, BH), dim3(32, 8)>>>(ck);

    // 4) Attention (SIMT fp32)
    attn_kernel<<<dim3(SEQ / 64, BH), 256, ATT_SMEM>>>(cv);

    // 5) Split attention output, then output projection
    split_kernel<<<(MROWS * DM / 4 + 255) / 256, 256>>>(gatt, ahi, alo, MROWS * DM / 4);
    gemm_mma<<<dim3(8, 16, 1), 256, GSMEM>>>(ahi, alo,
                                             whi + (size_t)3 * DM * DM, wlo + (size_t)3 * DM * DM,
                                             bo, bo, bo, out, out, out, 0);
}

// round 7
// speedup vs baseline: 2.9229x; 2.0330x over previous
#include <cuda_runtime.h>
#include <cuda_bf16.h>
#include <cstdint>

#define DM     1024
#define NHEADS 16
#define HD     64
#define BATCH  2
#define SEQ    1024
#define LCACHE 1024
#define TTOT   2048
#define BH     (BATCH * NHEADS)   // 32
#define MROWS  (BATCH * SEQ)      // 2048

// ---------------------------------------------------------------------------
// Scratch (device globals; no allocation allowed)
// ---------------------------------------------------------------------------
__device__ __nv_bfloat16 g_xhi[MROWS * DM], g_xlo[MROWS * DM];
__device__ __nv_bfloat16 g_whi[4 * DM * DM], g_wlo[4 * DM * DM];
__device__ __nv_bfloat16 g_qhi[BH * SEQ * HD],  g_qlo[BH * SEQ * HD];
__device__ __nv_bfloat16 g_khi[BH * TTOT * HD], g_klo[BH * TTOT * HD];
__device__ __nv_bfloat16 g_vhi[BH * TTOT * HD], g_vlo[BH * TTOT * HD];
__device__ __nv_bfloat16 g_ahi[MROWS * DM], g_alo[MROWS * DM];

// ---------------------------------------------------------------------------
// PTX helpers — baseline ISA only (compute_103-safe)
// ---------------------------------------------------------------------------
__device__ __forceinline__ uint32_t smem_u32(const void* p) {
    uint32_t a;
    asm("{ .reg .u64 t; cvta.to.shared.u64 t, %1; cvt.u32.u64 %0, t; }"
        : "=r"(a) : "l"(p));
    return a;
}
__device__ __forceinline__ void cp16(uint32_t d, const void* s) {
    asm volatile("cp.async.cg.shared.global [%0], [%1], 16;" :: "r"(d), "l"(s) : "memory");
}
__device__ __forceinline__ void cp_commit() {
    asm volatile("cp.async.commit_group;" ::: "memory");
}
template <int N> __device__ __forceinline__ void cp_wait() {
    asm volatile("cp.async.wait_group %0;" :: "n"(N) : "memory");
}
__device__ __forceinline__ void ldmx4(uint32_t* r, uint32_t a) {
    asm volatile("ldmatrix.sync.aligned.m8n8.x4.shared.b16 {%0,%1,%2,%3}, [%4];"
        : "=r"(r[0]), "=r"(r[1]), "=r"(r[2]), "=r"(r[3]) : "r"(a));
}
__device__ __forceinline__ void ldmx4t(uint32_t* r, uint32_t a) {
    asm volatile("ldmatrix.sync.aligned.m8n8.x4.trans.shared.b16 {%0,%1,%2,%3}, [%4];"
        : "=r"(r[0]), "=r"(r[1]), "=r"(r[2]), "=r"(r[3]) : "r"(a));
}
__device__ __forceinline__ void ldmx2(uint32_t* r, uint32_t a) {
    asm volatile("ldmatrix.sync.aligned.m8n8.x2.shared.b16 {%0,%1}, [%2];"
        : "=r"(r[0]), "=r"(r[1]) : "r"(a));
}
__device__ __forceinline__ void mma16816(float* d, const uint32_t* a, const uint32_t* b) {
    asm volatile(
        "mma.sync.aligned.m16n8k16.row.col.f32.bf16.bf16.f32 "
        "{%0,%1,%2,%3}, {%4,%5,%6,%7}, {%8,%9}, {%0,%1,%2,%3};"
        : "+f"(d[0]), "+f"(d[1]), "+f"(d[2]), "+f"(d[3])
        : "r"(a[0]), "r"(a[1]), "r"(a[2]), "r"(a[3]), "r"(b[0]), "r"(b[1]));
}
__device__ __forceinline__ float ex2f(float x) {
    float y;
    asm("ex2.approx.f32 %0, %1;" : "=f"(y) : "f"(x));
    return y;
}
__device__ __forceinline__ uint32_t pack_hi(float a, float b, __nv_bfloat16& ha, __nv_bfloat16& hb) {
    ha = __float2bfloat16_rn(a);
    hb = __float2bfloat16_rn(b);
    __nv_bfloat162 t = __halves2bfloat162(ha, hb);
    return *(uint32_t*)&t;
}

// ---------------------------------------------------------------------------
// hi/lo split kernels
// ---------------------------------------------------------------------------
__global__ void split_kernel(const float* __restrict__ in,
                             __nv_bfloat16* __restrict__ hi,
                             __nv_bfloat16* __restrict__ lo, int n4)
{
    int i = blockIdx.x * blockDim.x + threadIdx.x;
    if (i >= n4) return;
    float4 v = ((const float4*)in)[i];
    __nv_bfloat16 h0 = __float2bfloat16_rn(v.x);
    __nv_bfloat16 h1 = __float2bfloat16_rn(v.y);
    __nv_bfloat16 h2 = __float2bfloat16_rn(v.z);
    __nv_bfloat16 h3 = __float2bfloat16_rn(v.w);
    __nv_bfloat16 l0 = __float2bfloat16_rn(v.x - __bfloat162float(h0));
    __nv_bfloat16 l1 = __float2bfloat16_rn(v.y - __bfloat162float(h1));
    __nv_bfloat16 l2 = __float2bfloat16_rn(v.z - __bfloat162float(h2));
    __nv_bfloat16 l3 = __float2bfloat16_rn(v.w - __bfloat162float(h3));
    ((__nv_bfloat162*)hi)[2 * i]     = __halves2bfloat162(h0, h1);
    ((__nv_bfloat162*)hi)[2 * i + 1] = __halves2bfloat162(h2, h3);
    ((__nv_bfloat162*)lo)[2 * i]     = __halves2bfloat162(l0, l1);
    ((__nv_bfloat162*)lo)[2 * i + 1] = __halves2bfloat162(l2, l3);
}

__global__ void split_w4(const float* __restrict__ w0, const float* __restrict__ w1,
                         const float* __restrict__ w2, const float* __restrict__ w3,
                         __nv_bfloat16* __restrict__ hi, __nv_bfloat16* __restrict__ lo)
{
    int p = blockIdx.y;
    const float* src = (p == 0) ? w0 : (p == 1) ? w1 : (p == 2) ? w2 : w3;
    size_t off2 = (size_t)p * (DM * DM / 2);
    int i = blockIdx.x * blockDim.x + threadIdx.x;
    float4 v = ((const float4*)src)[i];
    __nv_bfloat16 h0 = __float2bfloat16_rn(v.x);
    __nv_bfloat16 h1 = __float2bfloat16_rn(v.y);
    __nv_bfloat16 h2 = __float2bfloat16_rn(v.z);
    __nv_bfloat16 h3 = __float2bfloat16_rn(v.w);
    __nv_bfloat16 l0 = __float2bfloat16_rn(v.x - __bfloat162float(h0));
    __nv_bfloat16 l1 = __float2bfloat16_rn(v.y - __bfloat162float(h1));
    __nv_bfloat16 l2 = __float2bfloat16_rn(v.z - __bfloat162float(h2));
    __nv_bfloat16 l3 = __float2bfloat16_rn(v.w - __bfloat162float(h3));
    ((__nv_bfloat162*)hi)[off2 + 2 * i]     = __halves2bfloat162(h0, h1);
    ((__nv_bfloat162*)hi)[off2 + 2 * i + 1] = __halves2bfloat162(h2, h3);
    ((__nv_bfloat162*)lo)[off2 + 2 * i]     = __halves2bfloat162(l0, l1);
    ((__nv_bfloat162*)lo)[off2 + 2 * i + 1] = __halves2bfloat162(l2, l3);
}

// Convert fp32 KV cache -> bf16 hi/lo planes at t < LCACHE of [bh][TTOT][64]
__global__ void convert_cache(const float* __restrict__ ck, const float* __restrict__ cv)
{
    const int which = blockIdx.y;
    const float* src = which ? cv : ck;
    __nv_bfloat16* hi = which ? g_vhi : g_khi;
    __nv_bfloat16* lo = which ? g_vlo : g_klo;
    int i = blockIdx.x * blockDim.x + threadIdx.x;   // float4 over BH*LCACHE*HD/4
    float4 v = ((const float4*)src)[i];
    int el = i * 4;
    int bh = el >> 16;                // LCACHE*HD = 65536
    int rest = el & 65535;
    size_t o = (size_t)bh * (TTOT * HD) + rest;
    __nv_bfloat16 h0 = __float2bfloat16_rn(v.x);
    __nv_bfloat16 h1 = __float2bfloat16_rn(v.y);
    __nv_bfloat16 h2 = __float2bfloat16_rn(v.z);
    __nv_bfloat16 h3 = __float2bfloat16_rn(v.w);
    __nv_bfloat16 l0 = __float2bfloat16_rn(v.x - __bfloat162float(h0));
    __nv_bfloat16 l1 = __float2bfloat16_rn(v.y - __bfloat162float(h1));
    __nv_bfloat16 l2 = __float2bfloat16_rn(v.z - __bfloat162float(h2));
    __nv_bfloat16 l3 = __float2bfloat16_rn(v.w - __bfloat162float(h3));
    *(__nv_bfloat162*)(hi + o)     = __halves2bfloat162(h0, h1);
    *(__nv_bfloat162*)(hi + o + 2) = __halves2bfloat162(h2, h3);
    *(__nv_bfloat162*)(lo + o)     = __halves2bfloat162(l0, l1);
    *(__nv_bfloat162*)(lo + o + 2) = __halves2bfloat162(l2, l3);
}

// ---------------------------------------------------------------------------
// Warp-MMA bf16 GEMM (hi/lo 3-term). headwise=1 writes bf16 hi/lo Q/K/V planes
// (z selects); headwise=0 writes fp32 to fout.
// ---------------------------------------------------------------------------
#define ST       3
#define CHUNKS   32
#define ROWPAD   80
#define PLANE_B  (128 * ROWPAD)
#define STAGE_B  (4 * PLANE_B)
#define GSMEM    (ST * STAGE_B)

__global__ __launch_bounds__(256, 1)
void gemm_mma(const __nv_bfloat16* __restrict__ Ahi, const __nv_bfloat16* __restrict__ Alo,
              const __nv_bfloat16* __restrict__ Whi, const __nv_bfloat16* __restrict__ Wlo,
              const float* __restrict__ b0, const float* __restrict__ b1, const float* __restrict__ b2,
              __nv_bfloat16* __restrict__ ph0, __nv_bfloat16* __restrict__ pl0,
              __nv_bfloat16* __restrict__ ph1, __nv_bfloat16* __restrict__ pl1,
              __nv_bfloat16* __restrict__ ph2, __nv_bfloat16* __restrict__ pl2,
              float* __restrict__ fout, int headwise)
{
    extern __shared__ char smem[];
    const uint32_t sb = smem_u32(smem);
    const int tid = threadIdx.x, wid = tid >> 5, lane = tid & 31;
    const int n0 = blockIdx.x * 128, m0 = blockIdx.y * 128, z = blockIdx.z;
    const __nv_bfloat16* Wh = Whi + (size_t)z * DM * DM;
    const __nv_bfloat16* Wl = Wlo + (size_t)z * DM * DM;
    const float* bias = (z == 0) ? b0 : (z == 1) ? b1 : b2;

    const int wm = wid & 1;
    const int wn = wid >> 1;

    auto load_chunk = [&](int stage, int koff) {
        const uint32_t base = sb + stage * STAGE_B;
#pragma unroll
        for (int it = 0; it < 8; it++) {
            int g = it * 256 + tid;
            int plane = g >> 9;
            int row = (g >> 2) & 127;
            int c = g & 3;
            uint32_t dst = base + plane * PLANE_B + row * ROWPAD + c * 16;
            const __nv_bfloat16* src;
            if (plane == 0)      src = Ahi + (size_t)(m0 + row) * DM + koff + c * 8;
            else if (plane == 1) src = Alo + (size_t)(m0 + row) * DM + koff + c * 8;
            else if (plane == 2) src = Wh  + (size_t)(n0 + row) * DM + koff + c * 8;
            else                 src = Wl  + (size_t)(n0 + row) * DM + koff + c * 8;
            cp16(dst, src);
        }
        cp_commit();
    };

    load_chunk(0, 0);
    load_chunk(1, 32);

    float acc[4][4][4];
#pragma unroll
    for (int i = 0; i < 4; i++)
#pragma unroll
        for (int j = 0; j < 4; j++)
#pragma unroll
            for (int r = 0; r < 4; r++) acc[i][j][r] = 0.f;

    const int lr16 = lane & 15, lc16 = lane >> 4;
    const int br8 = lane & 7, bc8 = (lane >> 3) & 1;

    for (int i = 0; i < CHUNKS; i++) {
        if (i + 2 < CHUNKS) load_chunk((i + 2) % ST, (i + 2) * 32);
        else cp_commit();
        cp_wait<2>();
        __syncthreads();

        const uint32_t stb = sb + (i % ST) * STAGE_B;
#pragma unroll
        for (int ks = 0; ks < 2; ks++) {
            uint32_t ah[4][4], al[4][4];
#pragma unroll
            for (int mi = 0; mi < 4; mi++) {
                uint32_t ad = stb + (wm * 64 + mi * 16 + lr16) * ROWPAD + ks * 32 + lc16 * 16;
                ldmx4(ah[mi], ad);
                ldmx4(al[mi], ad + PLANE_B);
            }
            uint32_t bh[4][2], bl[4][2];
#pragma unroll
            for (int nj = 0; nj < 4; nj++) {
                uint32_t bd = stb + 2 * PLANE_B + (wn * 32 + nj * 8 + br8) * ROWPAD + ks * 32 + bc8 * 16;
                ldmx2(bh[nj], bd);
                ldmx2(bl[nj], bd + PLANE_B);
            }
#pragma unroll
            for (int mi = 0; mi < 4; mi++)
#pragma unroll
                for (int nj = 0; nj < 4; nj++) {
                    mma16816(acc[mi][nj], ah[mi], bh[nj]);
                    mma16816(acc[mi][nj], ah[mi], bl[nj]);
                    mma16816(acc[mi][nj], al[mi], bh[nj]);
                }
        }
        __syncthreads();
    }

    // epilogue
    __nv_bfloat16* ph = (z == 0) ? ph0 : (z == 1) ? ph1 : ph2;
    __nv_bfloat16* pl = (z == 0) ? pl0 : (z == 1) ? pl1 : pl2;
    const int tstr = (z == 0) ? SEQ : TTOT;
    const int toff = (z == 0) ? 0 : LCACHE;

#pragma unroll
    for (int nj = 0; nj < 4; nj++) {
        const int n = n0 + wn * 32 + nj * 8 + (lane & 3) * 2;
        const float bx = bias[n], by = bias[n + 1];
        const int h = n >> 6, d = n & 63;
#pragma unroll
        for (int mi = 0; mi < 4; mi++) {
#pragma unroll
            for (int half = 0; half < 2; half++) {
                const int m = m0 + wm * 64 + mi * 16 + (lane >> 2) + half * 8;
                float vx = acc[mi][nj][half * 2] + bx;
                float vy = acc[mi][nj][half * 2 + 1] + by;
                if (headwise) {
                    int b = m >> 10, s = m & 1023;
                    size_t ad = (((size_t)b * NHEADS + h) * tstr + toff + s) * HD + d;
                    __nv_bfloat16 hx = __float2bfloat16_rn(vx);
                    __nv_bfloat16 hy = __float2bfloat16_rn(vy);
                    *(__nv_bfloat162*)(ph + ad) = __halves2bfloat162(hx, hy);
                    *(__nv_bfloat162*)(pl + ad) = __halves2bfloat162(
                        __float2bfloat16_rn(vx - __bfloat162float(hx)),
                        __float2bfloat16_rn(vy - __bfloat162float(hy)));
                } else {
                    *(float2*)&fout[(size_t)m * DM + n] = make_float2(vx, vy);
                }
            }
        }
    }
}

// ---------------------------------------------------------------------------
// Tensor-core flash attention. CTA = (bh, 64-row q tile), 128 threads (4 warps
// x 16 q rows). KV tiles of 64, double-buffered cp.async. bf16 hi/lo 3-term
// for both S = Q K^T and O += P V. Online softmax in registers.
// ---------------------------------------------------------------------------
#define ASTRIDE 144                  // bytes per 64-bf16 row (128B data + 16B pad)
#define APLANE  (64 * ASTRIDE)       // 9216
#define AKVOFF  (2 * APLANE)
#define ASMEM   (2 * APLANE + 2 * 4 * APLANE)   // Q hi/lo + 2 stages x 4 planes = 92160
#define SCLOG2  0.18033688011112042f // 0.125 * log2(e)

__global__ __launch_bounds__(128, 2)
void attn_tc()
{
    extern __shared__ char smem[];
    const uint32_t sb = smem_u32(smem);
    const int tid = threadIdx.x, w = tid >> 5, lane = tid & 31;
    const int bh = blockIdx.x;
    const int qt = 15 - blockIdx.y;       // long tiles first
    const int q0 = qt * 64;
    const int nt = qt + 17;

    // Q tile (2 planes)
#pragma unroll
    for (int it = 0; it < 8; it++) {
        int g = it * 128 + tid;
        int plane = g >> 9, row = (g >> 3) & 63, gc = g & 7;
        const __nv_bfloat16* src = (plane ? g_qlo : g_qhi)
            + ((size_t)bh * SEQ + q0 + row) * HD + gc * 8;
        cp16(sb + plane * APLANE + row * ASTRIDE + gc * 16, src);
    }
    cp_commit();

    auto load_kv = [&](int kt, int st) {
        uint32_t base = sb + AKVOFF + st * (4 * APLANE);
        int t0 = kt * 64;
#pragma unroll
        for (int it = 0; it < 16; it++) {
            int g = it * 128 + tid;
            int plane = g >> 9, row = (g >> 3) & 63, gc = g & 7;
            size_t off = ((size_t)bh * TTOT + t0 + row) * HD + gc * 8;
            const __nv_bfloat16* src;
            if (plane == 0)      src = g_khi + off;
            else if (plane == 1) src = g_klo + off;
            else if (plane == 2) src = g_vhi + off;
            else                 src = g_vlo + off;
            cp16(base + plane * APLANE + row * ASTRIDE + gc * 16, src);
        }
        cp_commit();
    };
    load_kv(0, 0);
    cp_wait<0>();
    __syncthreads();

    // Q fragments (A layout), preloaded once
    uint32_t qh[4][4], ql[4][4];
#pragma unroll
    for (int kc = 0; kc < 4; kc++) {
        uint32_t qa = sb + (w * 16 + (lane & 15)) * ASTRIDE + kc * 32 + (lane >> 4) * 16;
        ldmx4(qh[kc], qa);
        ldmx4(ql[kc], qa + APLANE);
    }

    float oacc[8][4];
#pragma unroll
    for (int i = 0; i < 8; i++)
#pragma unroll
        for (int j = 0; j < 4; j++) oacc[i][j] = 0.f;
    float mrow[2] = {-1e30f, -1e30f}, lrow[2] = {0.f, 0.f};

    for (int kt = 0; kt < nt; kt++) {
        const int st = kt & 1;
        if (kt + 1 < nt) load_kv(kt + 1, st ^ 1);
        const uint32_t kbase = sb + AKVOFF + st * (4 * APLANE);
        const uint32_t vbase = kbase + 2 * APLANE;

        // ---- S = Q K^T (3-term)
        float sacc[8][4];
#pragma unroll
        for (int nb = 0; nb < 8; nb++) {
#pragma unroll
            for (int j = 0; j < 4; j++) sacc[nb][j] = 0.f;
        }
#pragma unroll
        for (int nb = 0; nb < 8; nb++) {
            uint32_t kh[8], kl[8];
            uint32_t ka = kbase + (nb * 8 + (lane & 7)) * ASTRIDE + (lane >> 3) * 16;
            ldmx4(kh, ka);  ldmx4(kh + 4, ka + 64);
            ldmx4(kl, ka + APLANE);  ldmx4(kl + 4, ka + APLANE + 64);
#pragma unroll
            for (int kc = 0; kc < 4; kc++) {
                mma16816(sacc[nb], qh[kc], &kh[kc * 2]);
                mma16816(sacc[nb], qh[kc], &kl[kc * 2]);
                mma16816(sacc[nb], ql[kc], &kh[kc * 2]);
            }
        }

        // ---- causal mask (only the last tile is partial: t_local > q_local)
        if (kt == nt - 1) {
            const int qloc = w * 16 + (lane >> 2);
#pragma unroll
            for (int nb = 0; nb < 8; nb++) {
#pragma unroll
                for (int c = 0; c < 4; c++) {
                    int tl = nb * 8 + (lane & 3) * 2 + (c & 1);
                    int qr = qloc + (c >> 1) * 8;
                    if (tl > qr) sacc[nb][c] = -1e30f;
                }
            }
        }

        // ---- online softmax (2 rows per thread)
        uint32_t phf[4][4], plf[4][4];
#pragma unroll
        for (int i = 0; i < 2; i++) {
            float mx = -1e30f;
#pragma unroll
            for (int nb = 0; nb < 8; nb++)
                mx = fmaxf(mx, fmaxf(sacc[nb][2 * i], sacc[nb][2 * i + 1]));
            mx = fmaxf(mx, __shfl_xor_sync(0xffffffffu, mx, 1));
            mx = fmaxf(mx, __shfl_xor_sync(0xffffffffu, mx, 2));
            float mn = fmaxf(mrow[i], mx);
            float f = ex2f((mrow[i] - mn) * SCLOG2);
            mrow[i] = mn;
            float sum = 0.f;
#pragma unroll
            for (int nb = 0; nb < 8; nb++) {
                float p0 = ex2f((sacc[nb][2 * i] - mn) * SCLOG2);
                float p1 = ex2f((sacc[nb][2 * i + 1] - mn) * SCLOG2);
                sacc[nb][2 * i] = p0;
                sacc[nb][2 * i + 1] = p1;
                sum += p0 + p1;
            }
            sum += __shfl_xor_sync(0xffffffffu, sum, 1);
            sum += __shfl_xor_sync(0xffffffffu, sum, 2);
            lrow[i] = lrow[i] * f + sum;
#pragma unroll
            for (int nbd = 0; nbd < 8; nbd++) {
                oacc[nbd][2 * i] *= f;
                oacc[nbd][2 * i + 1] *= f;
            }
        }

        // ---- P -> A fragments (register-only), hi/lo
#pragma unroll
        for (int kc = 0; kc < 4; kc++) {
#pragma unroll
            for (int q = 0; q < 4; q++) {
                int nb = 2 * kc + (q >> 1);
                float a = sacc[nb][(q & 1) * 2];
                float b = sacc[nb][(q & 1) * 2 + 1];
                __nv_bfloat16 ha, hb2;
                phf[kc][q] = pack_hi(a, b, ha, hb2);
                __nv_bfloat162 lo2 = __halves2bfloat162(
                    __float2bfloat16_rn(a - __bfloat162float(ha)),
                    __float2bfloat16_rn(b - __bfloat162float(hb2)));
                plf[kc][q] = *(uint32_t*)&lo2;
            }
        }

        // ---- O += P V (3-term), V via ldmatrix.trans
#pragma unroll
        for (int kc = 0; kc < 4; kc++) {
#pragma unroll
            for (int dp = 0; dp < 4; dp++) {
                uint32_t vh[4], vl[4];
                uint32_t va = vbase + (kc * 16 + ((lane >> 3) & 1) * 8 + (lane & 7)) * ASTRIDE
                            + (dp * 16 + (lane >> 4) * 8) * 2;
                ldmx4t(vh, va);
                ldmx4t(vl, va + APLANE);
                mma16816(oacc[dp * 2],     phf[kc], &vh[0]);
                mma16816(oacc[dp * 2],     phf[kc], &vl[0]);
                mma16816(oacc[dp * 2],     plf[kc], &vh[0]);
                mma16816(oacc[dp * 2 + 1], phf[kc], &vh[2]);
                mma16816(oacc[dp * 2 + 1], phf[kc], &vl[2]);
                mma16816(oacc[dp * 2 + 1], plf[kc], &vh[2]);
            }
        }

        cp_wait<0>();
        __syncthreads();
    }

    // ---- epilogue: normalize, write bf16 hi/lo planes for oproj
    const int b = bh >> 4, h = bh & 15;
#pragma unroll
    for (int i = 0; i < 2; i++) {
        float inv = 1.f / lrow[i];
        int srow = q0 + w * 16 + (lane >> 2) + i * 8;
        size_t mbase = ((size_t)b * SEQ + srow) * DM + h * HD + (lane & 3) * 2;
#pragma unroll
        for (int nbd = 0; nbd < 8; nbd++) {
            float v0 = oacc[nbd][2 * i] * inv;
            float v1 = oacc[nbd][2 * i + 1] * inv;
            __nv_bfloat16 h0 = __float2bfloat16_rn(v0);
            __nv_bfloat16 h1 = __float2bfloat16_rn(v1);
            *(__nv_bfloat162*)(g_ahi + mbase + nbd * 8) = __halves2bfloat162(h0, h1);
            *(__nv_bfloat162*)(g_alo + mbase + nbd * 8) = __halves2bfloat162(
                __float2bfloat16_rn(v0 - __bfloat162float(h0)),
                __float2bfloat16_rn(v1 - __bfloat162float(h1)));
        }
    }
}

// ---------------------------------------------------------------------------
// launch
// ---------------------------------------------------------------------------
extern "C" void kernel_launch(void* const* d_in, const int* in_sizes, int n_in,
                              void* d_out, int out_size)
{
    const float* x  = (const float*)d_in[0];
    const float* ck = (const float*)d_in[1];
    const float* cv = (const float*)d_in[2];
    const float* Wq = (const float*)d_in[3];
    const float* bq = (const float*)d_in[4];
    const float* Wk = (const float*)d_in[5];
    const float* bk = (const float*)d_in[6];
    const float* Wv = (const float*)d_in[7];
    const float* bv = (const float*)d_in[8];
    const float* Wo = (const float*)d_in[9];
    const float* bo = (const float*)d_in[10];
    float* out = (float*)d_out;

    __nv_bfloat16 *xhi, *xlo, *whi, *wlo, *ahi, *alo;
    __nv_bfloat16 *qhi, *qlo, *khi, *klo, *vhi, *vlo;
    cudaGetSymbolAddress((void**)&xhi, g_xhi);
    cudaGetSymbolAddress((void**)&xlo, g_xlo);
    cudaGetSymbolAddress((void**)&whi, g_whi);
    cudaGetSymbolAddress((void**)&wlo, g_wlo);
    cudaGetSymbolAddress((void**)&ahi, g_ahi);
    cudaGetSymbolAddress((void**)&alo, g_alo);
    cudaGetSymbolAddress((void**)&qhi, g_qhi);
    cudaGetSymbolAddress((void**)&qlo, g_qlo);
    cudaGetSymbolAddress((void**)&khi, g_khi);
    cudaGetSymbolAddress((void**)&klo, g_klo);
    cudaGetSymbolAddress((void**)&vhi, g_vhi);
    cudaGetSymbolAddress((void**)&vlo, g_vlo);

    cudaFuncSetAttribute(gemm_mma, cudaFuncAttributeMaxDynamicSharedMemorySize, GSMEM);
    cudaFuncSetAttribute(attn_tc, cudaFuncAttributeMaxDynamicSharedMemorySize, ASMEM);

    // 1) splits + cache conversion
    split_kernel<<<(MROWS * DM / 4 + 255) / 256, 256>>>(x, xhi, xlo, MROWS * DM / 4);
    split_w4<<<dim3(DM * DM / 4 / 256, 4), 256>>>(Wq, Wk, Wv, Wo, whi, wlo);
    convert_cache<<<dim3(BH * LCACHE * HD / 4 / 256, 2), 256>>>(ck, cv);

    // 2) QKV projections -> bf16 hi/lo Q/K/V planes
    gemm_mma<<<dim3(8, 16, 3), 256, GSMEM>>>(xhi, xlo, whi, wlo,
                                             bq, bk, bv,
                                             qhi, qlo, khi, klo, vhi, vlo,
                                             nullptr, 1);

    // 3) tensor-core flash attention -> bf16 hi/lo planes
    attn_tc<<<dim3(BH, 16), 128, ASMEM>>>();

    // 4) output projection -> fp32 d_out
    gemm_mma<<<dim3(8, 16, 1), 256, GSMEM>>>(ahi, alo,
                                             whi + (size_t)3 * DM * DM, wlo + (size_t)3 * DM * DM,
                                             bo, bo, bo,
                                             nullptr, nullptr, nullptr, nullptr, nullptr, nullptr,
                                             out, 0);
}